// round 1
// baseline (speedup 1.0000x reference)
#include <cuda_runtime.h>
#include <cuda_bf16.h>
#include <math_constants.h>

#define BATCH 512
#define SEQ   256
#define EMBD  384
#define HEAD  64
#define MROWS (BATCH * SEQ)   // 131072

// Scratch for projected Q, K, V (allocation-free rule: device globals)
__device__ float g_Q[MROWS * HEAD];
__device__ float g_K[MROWS * HEAD];
__device__ float g_V[MROWS * HEAD];

// ---------------------------------------------------------------------------
// Kernel 1: QKV projection. Tiled SGEMM: [131072 x 384] @ [384 x 64] + bias.
// grid.x = 2048 (row tiles of 64), grid.y = 3 (Q/K/V). 256 threads, 4x4 microtile.
// ---------------------------------------------------------------------------
#define BM 64
#define BK 16

__global__ __launch_bounds__(256) void qkv_proj(
    const float* __restrict__ x,
    const float* __restrict__ Wq, const float* __restrict__ bq,
    const float* __restrict__ Wk, const float* __restrict__ bk,
    const float* __restrict__ Wv, const float* __restrict__ bv)
{
    __shared__ float As[BK][BM + 4];   // x tile, transposed (k-major), padded
    __shared__ float Bs[BK][HEAD];     // W tile

    const int which = blockIdx.y;
    const float* W;
    const float* bias;
    float* out;
    if (which == 0)      { W = Wq; bias = bq; out = g_Q; }
    else if (which == 1) { W = Wk; bias = bk; out = g_K; }
    else                 { W = Wv; bias = bv; out = g_V; }

    const int m0  = blockIdx.x * BM;
    const int tid = threadIdx.x;
    const int tx  = tid & 15;   // 0..15  -> 4 output cols
    const int ty  = tid >> 4;   // 0..15  -> 4 output rows

    float acc[4][4] = {};

    // per-thread load coordinates
    const int a_row = tid >> 2;          // 0..63
    const int a_kc  = (tid & 3) * 4;     // 0,4,8,12
    const int b_row = tid >> 4;          // 0..15
    const int b_nc  = (tid & 15) * 4;    // 0..60

    for (int k0 = 0; k0 < EMBD; k0 += BK) {
        // load x tile [64 x 16], store transposed into As[k][m]
        {
            float4 v = *(const float4*)(x + (size_t)(m0 + a_row) * EMBD + k0 + a_kc);
            As[a_kc + 0][a_row] = v.x;
            As[a_kc + 1][a_row] = v.y;
            As[a_kc + 2][a_row] = v.z;
            As[a_kc + 3][a_row] = v.w;
        }
        // load W tile [16 x 64]
        {
            *(float4*)&Bs[b_row][b_nc] =
                *(const float4*)(W + (size_t)(k0 + b_row) * HEAD + b_nc);
        }
        __syncthreads();

        #pragma unroll
        for (int k = 0; k < BK; k++) {
            float4 a  = *(float4*)&As[k][ty * 4];
            float4 bb = *(float4*)&Bs[k][tx * 4];
            acc[0][0] += a.x * bb.x; acc[0][1] += a.x * bb.y; acc[0][2] += a.x * bb.z; acc[0][3] += a.x * bb.w;
            acc[1][0] += a.y * bb.x; acc[1][1] += a.y * bb.y; acc[1][2] += a.y * bb.z; acc[1][3] += a.y * bb.w;
            acc[2][0] += a.z * bb.x; acc[2][1] += a.z * bb.y; acc[2][2] += a.z * bb.z; acc[2][3] += a.z * bb.w;
            acc[3][0] += a.w * bb.x; acc[3][1] += a.w * bb.y; acc[3][2] += a.w * bb.z; acc[3][3] += a.w * bb.w;
        }
        __syncthreads();
    }

    // epilogue: add bias, store
    float4 bb = *(const float4*)(bias + tx * 4);
    #pragma unroll
    for (int i = 0; i < 4; i++) {
        float4 o;
        o.x = acc[i][0] + bb.x;
        o.y = acc[i][1] + bb.y;
        o.z = acc[i][2] + bb.z;
        o.w = acc[i][3] + bb.w;
        *(float4*)(out + (size_t)(m0 + ty * 4 + i) * HEAD + tx * 4) = o;
    }
}

// ---------------------------------------------------------------------------
// Kernel 2: fused causal attention + online softmax.
// One CTA per batch. K,V staged in 128KB dynamic smem (all reads are
// warp-uniform broadcasts). 128 threads; thread i processes rows i and 255-i
// so every warp's total key-iteration count is exactly 288 (balanced).
// ---------------------------------------------------------------------------
__global__ __launch_bounds__(128) void attn_kernel(float* __restrict__ out)
{
    extern __shared__ float smem[];
    float* Ks = smem;                 // [256][64]
    float* Vs = smem + SEQ * HEAD;    // [256][64]

    const int b = blockIdx.x;

    // stage K, V for this batch
    {
        const float4* Kg = (const float4*)(g_K + (size_t)b * SEQ * HEAD);
        const float4* Vg = (const float4*)(g_V + (size_t)b * SEQ * HEAD);
        float4* Ks4 = (float4*)Ks;
        float4* Vs4 = (float4*)Vs;
        for (int i = threadIdx.x; i < SEQ * HEAD / 4; i += 128) {
            Ks4[i] = Kg[i];
            Vs4[i] = Vg[i];
        }
    }
    __syncthreads();

    const float qscale = 0.125f * 1.44269504088896340736f;  // SCALE * log2(e)

    #pragma unroll 1
    for (int pass = 0; pass < 2; pass++) {
        const int t = pass ? (SEQ - 1 - (int)threadIdx.x) : (int)threadIdx.x;

        // load and pre-scale q row
        float4 q[16];
        {
            const float4* Qg = (const float4*)(g_Q + ((size_t)b * SEQ + t) * HEAD);
            #pragma unroll
            for (int i = 0; i < 16; i++) {
                float4 v = Qg[i];
                v.x *= qscale; v.y *= qscale; v.z *= qscale; v.w *= qscale;
                q[i] = v;
            }
        }

        float m = -CUDART_INF_F;
        float l = 0.0f;
        float acc[64];
        #pragma unroll
        for (int h = 0; h < 64; h++) acc[h] = 0.0f;

        for (int s = 0; s <= t; s++) {
            // score (already in log2 domain)
            const float4* kr = (const float4*)(Ks + s * HEAD);
            float d0 = 0.f, d1 = 0.f, d2 = 0.f, d3 = 0.f;
            #pragma unroll
            for (int i = 0; i < 16; i++) {
                float4 kv = kr[i];
                d0 += q[i].x * kv.x;
                d1 += q[i].y * kv.y;
                d2 += q[i].z * kv.z;
                d3 += q[i].w * kv.w;
            }
            float dot = (d0 + d1) + (d2 + d3);

            float p;
            if (dot > m) {
                float c = exp2f(m - dot);   // 0 on first iter (m = -inf)
                l *= c;
                #pragma unroll
                for (int h = 0; h < 64; h++) acc[h] *= c;
                m = dot;
                p = 1.0f;
            } else {
                p = exp2f(dot - m);
            }
            l += p;

            const float4* vr = (const float4*)(Vs + s * HEAD);
            #pragma unroll
            for (int i = 0; i < 16; i++) {
                float4 vv = vr[i];
                acc[4 * i + 0] += p * vv.x;
                acc[4 * i + 1] += p * vv.y;
                acc[4 * i + 2] += p * vv.z;
                acc[4 * i + 3] += p * vv.w;
            }
        }

        const float inv = 1.0f / l;
        float4* og = (float4*)(out + ((size_t)b * SEQ + t) * HEAD);
        #pragma unroll
        for (int i = 0; i < 16; i++) {
            float4 o;
            o.x = acc[4 * i + 0] * inv;
            o.y = acc[4 * i + 1] * inv;
            o.z = acc[4 * i + 2] * inv;
            o.w = acc[4 * i + 3] * inv;
            og[i] = o;
        }
    }
}

// ---------------------------------------------------------------------------
extern "C" void kernel_launch(void* const* d_in, const int* in_sizes, int n_in,
                              void* d_out, int out_size)
{
    const float* x  = (const float*)d_in[0];
    const float* Wq = (const float*)d_in[1];
    const float* bq = (const float*)d_in[2];
    const float* Wk = (const float*)d_in[3];
    const float* bk = (const float*)d_in[4];
    const float* Wv = (const float*)d_in[5];
    const float* bv = (const float*)d_in[6];
    float* out = (float*)d_out;

    // QKV projection: 2048 row tiles x 3 matrices
    dim3 grid(MROWS / BM, 3);
    qkv_proj<<<grid, 256>>>(x, Wq, bq, Wk, bk, Wv, bv);

    // Fused attention: one block per batch, 128KB dynamic smem for K+V
    const int smem_bytes = 2 * SEQ * HEAD * (int)sizeof(float);  // 131072
    cudaFuncSetAttribute(attn_kernel,
                         cudaFuncAttributeMaxDynamicSharedMemorySize, smem_bytes);
    attn_kernel<<<BATCH, 128, smem_bytes>>>(out);
}

// round 3
// speedup vs baseline: 1.8060x; 1.8060x over previous
#include <cuda_runtime.h>
#include <cuda_bf16.h>
#include <math_constants.h>
#include <cstdint>

#define BATCH 512
#define SEQ   256
#define EMBD  384
#define HEAD  64
#define NQ    192            // Q|K|V concatenated output columns
#define MROWS (BATCH * SEQ)  // 131072
#define TMQ   128            // CTA M tile
#define TK    32             // K chunk

// Scratch (allocation-free rule: device globals)
__device__ float g_Q[MROWS * HEAD];
__device__ float g_K[MROWS * HEAD];
__device__ float g_V[MROWS * HEAD];
__device__ float g_W2[EMBD * NQ];   // k-major concat weights [k][n], tf32-rounded
__device__ float g_bc[NQ];          // concat bias (fp32)

// ---------------------------------------------------------------------------
// small PTX helpers
// ---------------------------------------------------------------------------
__device__ __forceinline__ uint32_t f2tf32(float f) {
    uint32_t r;
    asm("cvt.rna.tf32.f32 %0, %1;" : "=r"(r) : "f"(f));
    return r;
}
#define CP_ASYNC16(dst, src) \
    asm volatile("cp.async.cg.shared.global [%0], [%1], 16;" \
                 :: "r"((uint32_t)(dst)), "l"(src) : "memory")
#define CP_COMMIT() asm volatile("cp.async.commit_group;" ::: "memory")
#define CP_WAIT(n)  asm volatile("cp.async.wait_group %0;" :: "n"(n) : "memory")

__device__ __forceinline__ uint32_t smem_u32(const void* p) {
    uint32_t a;
    asm("{ .reg .u64 t; cvta.to.shared.u64 t, %1; cvt.u32.u64 %0, t; }"
        : "=r"(a) : "l"(p));
    return a;
}

__device__ __forceinline__ void mma_tf32(float* d, const uint32_t* a, const uint32_t* b) {
    asm volatile(
        "mma.sync.aligned.m16n8k8.row.col.f32.tf32.tf32.f32 "
        "{%0,%1,%2,%3}, {%4,%5,%6,%7}, {%8,%9}, {%0,%1,%2,%3};"
        : "+f"(d[0]), "+f"(d[1]), "+f"(d[2]), "+f"(d[3])
        : "r"(a[0]), "r"(a[1]), "r"(a[2]), "r"(a[3]), "r"(b[0]), "r"(b[1]));
}

// ---------------------------------------------------------------------------
// Kernel 0: concat + transpose weights to [k][n] (tf32-rounded), concat bias
// ---------------------------------------------------------------------------
__global__ __launch_bounds__(256) void prep_w(
    const float* __restrict__ Wq, const float* __restrict__ bq,
    const float* __restrict__ Wk, const float* __restrict__ bk,
    const float* __restrict__ Wv, const float* __restrict__ bv)
{
    int idx = blockIdx.x * 256 + threadIdx.x;
    if (idx < EMBD * NQ) {
        int k = idx / NQ;
        int n = idx - k * NQ;
        const float* W = (n < 64) ? Wq : (n < 128) ? Wk : Wv;
        float v = W[k * HEAD + (n & 63)];
        g_W2[idx] = __uint_as_float(f2tf32(v));
    }
    if (idx < NQ) {
        const float* bb = (idx < 64) ? bq : (idx < 128) ? bk : bv;
        g_bc[idx] = bb[idx & 63];
    }
}

// ---------------------------------------------------------------------------
// Kernel 1: QKV projection via mma.sync tf32.
// CTA: [128 x 192] output tile, 4 warps in 2x2, warp tile 64x96.
// Double-buffered cp.async staging; A padded to 36, B padded to 200 floats/row.
// ---------------------------------------------------------------------------
#define A_STRIDE 36
#define B_STRIDE 200
#define AS_OFF(st) ((st) ? (TMQ * A_STRIDE) : 0)                   // floats
#define BS_OFF(st) (2 * TMQ * A_STRIDE + ((st) ? (TK * B_STRIDE) : 0))
#define QKV_SMEM_FLOATS (2 * TMQ * A_STRIDE + 2 * TK * B_STRIDE)   // 22016
#define KCH (EMBD / TK)                                            // 12

__global__ __launch_bounds__(128, 1) void qkv_tc(const float* __restrict__ x)
{
    extern __shared__ float smem[];
    const int tid  = threadIdx.x;
    const int w    = tid >> 5;
    const int lane = tid & 31;
    const int g    = lane >> 2;     // groupID 0..7
    const int tg   = lane & 3;      // 0..3
    const int m0   = blockIdx.x * TMQ;
    const int m_w  = (w & 1) * 64;
    const int n_w  = (w >> 1) * 96;

    uint32_t sb = smem_u32(smem);

    float acc[4][12][4];
    #pragma unroll
    for (int mb = 0; mb < 4; mb++)
        #pragma unroll
        for (int nb = 0; nb < 12; nb++)
            #pragma unroll
            for (int i = 0; i < 4; i++) acc[mb][nb][i] = 0.0f;

    // ---- staging lambda-equivalents (macros for NCU line attribution) ----
    // A tile: 128 rows x 32 floats. Thread = row; 8 x 16B cp.async per row.
    // B tile: 32 rows x 192 floats = 1536 chunks; 12 per thread.
#define STAGE(kc, st) do {                                                     \
        const int _k0 = (kc) * TK;                                             \
        const char* _as = (const char*)(x + (size_t)(m0 + tid) * EMBD + _k0);  \
        uint32_t _ad = sb + 4 * (AS_OFF(st) + tid * A_STRIDE);                 \
        _Pragma("unroll")                                                      \
        for (int _j = 0; _j < 8; _j++)                                         \
            CP_ASYNC16(_ad + _j * 16, _as + _j * 16);                          \
        _Pragma("unroll")                                                      \
        for (int _j = 0; _j < 12; _j++) {                                      \
            int _idx = tid + _j * 128;                                         \
            int _k = _idx / 48;                                                \
            int _c = _idx - _k * 48;                                           \
            uint32_t _bd = sb + 4 * (BS_OFF(st) + _k * B_STRIDE + _c * 4);     \
            CP_ASYNC16(_bd, (const char*)(g_W2 + (size_t)(_k0 + _k) * NQ + _c * 4)); \
        }                                                                      \
        CP_COMMIT();                                                           \
    } while (0)

    STAGE(0, 0);

    for (int kc = 0; kc < KCH; kc++) {
        const int st = kc & 1;
        if (kc + 1 < KCH) {
            STAGE(kc + 1, st ^ 1);
            CP_WAIT(1);
        } else {
            CP_WAIT(0);
        }
        __syncthreads();

        const float* As = smem + AS_OFF(st);
        const float* Bs = smem + BS_OFF(st);

        #pragma unroll
        for (int s8 = 0; s8 < 4; s8++) {
            const int kk = s8 * 8;
            uint32_t bf[12][2];
            #pragma unroll
            for (int nb = 0; nb < 12; nb++) {
                bf[nb][0] = __float_as_uint(Bs[(kk + tg)     * B_STRIDE + n_w + nb * 8 + g]);
                bf[nb][1] = __float_as_uint(Bs[(kk + tg + 4) * B_STRIDE + n_w + nb * 8 + g]);
            }
            #pragma unroll
            for (int mb = 0; mb < 4; mb++) {
                const int rb = m_w + mb * 16;
                uint32_t af[4];
                af[0] = f2tf32(As[(rb + g)     * A_STRIDE + kk + tg]);
                af[1] = f2tf32(As[(rb + g + 8) * A_STRIDE + kk + tg]);
                af[2] = f2tf32(As[(rb + g)     * A_STRIDE + kk + tg + 4]);
                af[3] = f2tf32(As[(rb + g + 8) * A_STRIDE + kk + tg + 4]);
                #pragma unroll
                for (int nb = 0; nb < 12; nb++)
                    mma_tf32(acc[mb][nb], af, bf[nb]);
            }
        }
        __syncthreads();
    }
#undef STAGE

    // Epilogue: bias + scatter into g_Q / g_K / g_V
    #pragma unroll
    for (int nb = 0; nb < 12; nb++) {
        const int col = n_w + nb * 8 + tg * 2;
        const float2 bb = *(const float2*)(g_bc + col);
        float* base = (col < 64)  ? (g_Q + col)
                    : (col < 128) ? (g_K + (col - 64))
                                  : (g_V + (col - 128));
        #pragma unroll
        for (int mb = 0; mb < 4; mb++) {
            #pragma unroll
            for (int h = 0; h < 2; h++) {
                const int row = m0 + m_w + mb * 16 + g + h * 8;
                float2 o;
                o.x = acc[mb][nb][h * 2 + 0] + bb.x;
                o.y = acc[mb][nb][h * 2 + 1] + bb.y;
                *(float2*)(base + (size_t)row * HEAD) = o;
            }
        }
    }
}

// ---------------------------------------------------------------------------
// Kernel 2: fused causal attention, online softmax.
// 256 threads (2 warps/SMSP). Warp w handles row block (w<4 ? w : 11-w) so
// each SMSP's two warps have equal total causal-loop cost.
// ---------------------------------------------------------------------------
__global__ __launch_bounds__(256) void attn_kernel(float* __restrict__ out)
{
    extern __shared__ float asmem[];
    float* Ks = asmem;                 // [256][64]
    float* Vs = asmem + SEQ * HEAD;    // [256][64]

    const int b = blockIdx.x;

    {
        const float4* Kg = (const float4*)(g_K + (size_t)b * SEQ * HEAD);
        const float4* Vg = (const float4*)(g_V + (size_t)b * SEQ * HEAD);
        float4* Ks4 = (float4*)Ks;
        float4* Vs4 = (float4*)Vs;
        for (int i = threadIdx.x; i < SEQ * HEAD / 4; i += 256) {
            Ks4[i] = Kg[i];
            Vs4[i] = Vg[i];
        }
    }
    __syncthreads();

    const int w    = threadIdx.x >> 5;
    const int lane = threadIdx.x & 31;
    const int bl   = (w < 4) ? w : 11 - w;
    const int t    = bl * 32 + lane;

    const float qscale = 0.125f * 1.44269504088896340736f;  // SCALE * log2(e)

    float4 q[16];
    {
        const float4* Qg = (const float4*)(g_Q + ((size_t)b * SEQ + t) * HEAD);
        #pragma unroll
        for (int i = 0; i < 16; i++) {
            float4 v = Qg[i];
            v.x *= qscale; v.y *= qscale; v.z *= qscale; v.w *= qscale;
            q[i] = v;
        }
    }

    float m = -CUDART_INF_F;
    float l = 0.0f;
    float acc[64];
    #pragma unroll
    for (int h = 0; h < 64; h++) acc[h] = 0.0f;

    for (int s = 0; s <= t; s++) {
        const float4* kr = (const float4*)(Ks + s * HEAD);
        float d0 = 0.f, d1 = 0.f, d2 = 0.f, d3 = 0.f;
        #pragma unroll
        for (int i = 0; i < 16; i++) {
            float4 kv = kr[i];
            d0 += q[i].x * kv.x;
            d1 += q[i].y * kv.y;
            d2 += q[i].z * kv.z;
            d3 += q[i].w * kv.w;
        }
        float dot = (d0 + d1) + (d2 + d3);

        float p;
        if (dot > m) {
            float c = exp2f(m - dot);   // 0 on first iter
            l *= c;
            #pragma unroll
            for (int h = 0; h < 64; h++) acc[h] *= c;
            m = dot;
            p = 1.0f;
        } else {
            p = exp2f(dot - m);
        }
        l += p;

        const float4* vr = (const float4*)(Vs + s * HEAD);
        #pragma unroll
        for (int i = 0; i < 16; i++) {
            float4 vv = vr[i];
            acc[4 * i + 0] += p * vv.x;
            acc[4 * i + 1] += p * vv.y;
            acc[4 * i + 2] += p * vv.z;
            acc[4 * i + 3] += p * vv.w;
        }
    }

    const float inv = 1.0f / l;
    float4* og = (float4*)(out + ((size_t)b * SEQ + t) * HEAD);
    #pragma unroll
    for (int i = 0; i < 16; i++) {
        float4 o;
        o.x = acc[4 * i + 0] * inv;
        o.y = acc[4 * i + 1] * inv;
        o.z = acc[4 * i + 2] * inv;
        o.w = acc[4 * i + 3] * inv;
        og[i] = o;
    }
}

// ---------------------------------------------------------------------------
extern "C" void kernel_launch(void* const* d_in, const int* in_sizes, int n_in,
                              void* d_out, int out_size)
{
    const float* x  = (const float*)d_in[0];
    const float* Wq = (const float*)d_in[1];
    const float* bq = (const float*)d_in[2];
    const float* Wk = (const float*)d_in[3];
    const float* bk = (const float*)d_in[4];
    const float* Wv = (const float*)d_in[5];
    const float* bv = (const float*)d_in[6];
    float* out = (float*)d_out;

    prep_w<<<(EMBD * NQ + 255) / 256, 256>>>(Wq, bq, Wk, bk, Wv, bv);

    const int qkv_smem = QKV_SMEM_FLOATS * (int)sizeof(float);  // 88064
    cudaFuncSetAttribute(qkv_tc,
                         cudaFuncAttributeMaxDynamicSharedMemorySize, qkv_smem);
    qkv_tc<<<MROWS / TMQ, 128, qkv_smem>>>(x);

    const int smem_bytes = 2 * SEQ * HEAD * (int)sizeof(float);  // 131072
    cudaFuncSetAttribute(attn_kernel,
                         cudaFuncAttributeMaxDynamicSharedMemorySize, smem_bytes);
    attn_kernel<<<BATCH, 256, smem_bytes>>>(out);
}

// round 5
// speedup vs baseline: 3.6114x; 1.9997x over previous
#include <cuda_runtime.h>
#include <cuda_bf16.h>
#include <math_constants.h>
#include <cstdint>

#define BATCH 512
#define SEQ   256
#define EMBD  384
#define HEAD  64
#define NQ    192            // Q|K|V concatenated output columns
#define MROWS (BATCH * SEQ)  // 131072
#define TMQ   128            // CTA M tile
#define TK    32             // K chunk

// Scratch (allocation-free rule: device globals)
__device__ float g_Q[MROWS * HEAD];
__device__ float g_K[MROWS * HEAD];
__device__ float g_V[MROWS * HEAD];
__device__ float g_W2[EMBD * NQ];   // k-major concat weights [k][n], tf32-rounded
__device__ float g_bc[NQ];          // concat bias (fp32)

// ---------------------------------------------------------------------------
// small PTX helpers
// ---------------------------------------------------------------------------
__device__ __forceinline__ uint32_t f2tf32(float f) {
    uint32_t r;
    asm("cvt.rna.tf32.f32 %0, %1;" : "=r"(r) : "f"(f));
    return r;
}
__device__ __forceinline__ float f2tf32f(float f) {
    return __uint_as_float(f2tf32(f));
}
#define CP_ASYNC16(dst, src) \
    asm volatile("cp.async.cg.shared.global [%0], [%1], 16;" \
                 :: "r"((uint32_t)(dst)), "l"(src) : "memory")
#define CP_COMMIT() asm volatile("cp.async.commit_group;" ::: "memory")
#define CP_WAIT(n)  asm volatile("cp.async.wait_group %0;" :: "n"(n) : "memory")

__device__ __forceinline__ uint32_t smem_u32(const void* p) {
    uint32_t a;
    asm("{ .reg .u64 t; cvta.to.shared.u64 t, %1; cvt.u32.u64 %0, t; }"
        : "=r"(a) : "l"(p));
    return a;
}

__device__ __forceinline__ void mma_tf32(float* d, const uint32_t* a, const uint32_t* b) {
    asm volatile(
        "mma.sync.aligned.m16n8k8.row.col.f32.tf32.tf32.f32 "
        "{%0,%1,%2,%3}, {%4,%5,%6,%7}, {%8,%9}, {%0,%1,%2,%3};"
        : "+f"(d[0]), "+f"(d[1]), "+f"(d[2]), "+f"(d[3])
        : "r"(a[0]), "r"(a[1]), "r"(a[2]), "r"(a[3]), "r"(b[0]), "r"(b[1]));
}

// ---------------------------------------------------------------------------
// Kernel 0: concat + transpose weights to [k][n] (tf32-rounded), concat bias
// ---------------------------------------------------------------------------
__global__ __launch_bounds__(256) void prep_w(
    const float* __restrict__ Wq, const float* __restrict__ bq,
    const float* __restrict__ Wk, const float* __restrict__ bk,
    const float* __restrict__ Wv, const float* __restrict__ bv)
{
    int idx = blockIdx.x * 256 + threadIdx.x;
    if (idx < EMBD * NQ) {
        int k = idx / NQ;
        int n = idx - k * NQ;
        const float* W = (n < 64) ? Wq : (n < 128) ? Wk : Wv;
        g_W2[idx] = f2tf32f(W[k * HEAD + (n & 63)]);
    }
    if (idx < NQ) {
        const float* bb = (idx < 64) ? bq : (idx < 128) ? bk : bv;
        g_bc[idx] = bb[idx & 63];
    }
}

// ---------------------------------------------------------------------------
// Kernel 1: QKV projection via mma.sync tf32.
// CTA: [128 x 192] tile, 8 warps (2 M x 4 N), warp tile 64x48.
// Double-buffered cp.async staging.
// ---------------------------------------------------------------------------
#define A_STRIDE 36
#define B_STRIDE 200
#define AS_OFF(st) ((st) ? (TMQ * A_STRIDE) : 0)                   // floats
#define BS_OFF(st) (2 * TMQ * A_STRIDE + ((st) ? (TK * B_STRIDE) : 0))
#define QKV_SMEM_FLOATS (2 * TMQ * A_STRIDE + 2 * TK * B_STRIDE)   // 22016
#define KCH (EMBD / TK)                                            // 12

__global__ __launch_bounds__(256, 1) void qkv_tc(const float* __restrict__ x)
{
    extern __shared__ float smem[];
    const int tid  = threadIdx.x;
    const int w    = tid >> 5;
    const int lane = tid & 31;
    const int g    = lane >> 2;     // groupID 0..7
    const int tg   = lane & 3;      // 0..3
    const int m0   = blockIdx.x * TMQ;
    const int m_w  = (w & 1) * 64;
    const int n_w  = (w >> 1) * 48;

    uint32_t sb = smem_u32(smem);

    float acc[4][6][4];
    #pragma unroll
    for (int mb = 0; mb < 4; mb++)
        #pragma unroll
        for (int nb = 0; nb < 6; nb++)
            #pragma unroll
            for (int i = 0; i < 4; i++) acc[mb][nb][i] = 0.0f;

    // A tile: 128 rows x 32 floats = 1024 16B chunks, 4/thread.
    // B tile: 32 rows x 192 floats = 1536 16B chunks, 6/thread.
#define STAGE(kc, st) do {                                                     \
        const int _k0 = (kc) * TK;                                             \
        _Pragma("unroll")                                                      \
        for (int _j = 0; _j < 4; _j++) {                                       \
            int _idx = tid + _j * 256;                                         \
            int _r = _idx >> 3, _c = _idx & 7;                                 \
            uint32_t _ad = sb + 4 * (AS_OFF(st) + _r * A_STRIDE + _c * 4);     \
            CP_ASYNC16(_ad, (const char*)(x + (size_t)(m0 + _r) * EMBD + _k0 + _c * 4)); \
        }                                                                      \
        _Pragma("unroll")                                                      \
        for (int _j = 0; _j < 6; _j++) {                                       \
            int _idx = tid + _j * 256;                                         \
            int _k = _idx / 48;                                                \
            int _c = _idx - _k * 48;                                           \
            uint32_t _bd = sb + 4 * (BS_OFF(st) + _k * B_STRIDE + _c * 4);     \
            CP_ASYNC16(_bd, (const char*)(g_W2 + (size_t)(_k0 + _k) * NQ + _c * 4)); \
        }                                                                      \
        CP_COMMIT();                                                           \
    } while (0)

    STAGE(0, 0);

    for (int kc = 0; kc < KCH; kc++) {
        const int st = kc & 1;
        if (kc + 1 < KCH) {
            STAGE(kc + 1, st ^ 1);
            CP_WAIT(1);
        } else {
            CP_WAIT(0);
        }
        __syncthreads();

        const float* As = smem + AS_OFF(st);
        const float* Bs = smem + BS_OFF(st);

        #pragma unroll
        for (int s8 = 0; s8 < 4; s8++) {
            const int kk = s8 * 8;
            uint32_t bf[6][2];
            #pragma unroll
            for (int nb = 0; nb < 6; nb++) {
                bf[nb][0] = __float_as_uint(Bs[(kk + tg)     * B_STRIDE + n_w + nb * 8 + g]);
                bf[nb][1] = __float_as_uint(Bs[(kk + tg + 4) * B_STRIDE + n_w + nb * 8 + g]);
            }
            #pragma unroll
            for (int mb = 0; mb < 4; mb++) {
                const int rb = m_w + mb * 16;
                uint32_t af[4];
                af[0] = f2tf32(As[(rb + g)     * A_STRIDE + kk + tg]);
                af[1] = f2tf32(As[(rb + g + 8) * A_STRIDE + kk + tg]);
                af[2] = f2tf32(As[(rb + g)     * A_STRIDE + kk + tg + 4]);
                af[3] = f2tf32(As[(rb + g + 8) * A_STRIDE + kk + tg + 4]);
                #pragma unroll
                for (int nb = 0; nb < 6; nb++)
                    mma_tf32(acc[mb][nb], af, bf[nb]);
            }
        }
        __syncthreads();
    }
#undef STAGE

    // Epilogue: bias + scatter into g_Q / g_K / g_V
    #pragma unroll
    for (int nb = 0; nb < 6; nb++) {
        const int col = n_w + nb * 8 + tg * 2;
        const float2 bb = *(const float2*)(g_bc + col);
        float* base = (col < 64)  ? (g_Q + col)
                    : (col < 128) ? (g_K + (col - 64))
                                  : (g_V + (col - 128));
        #pragma unroll
        for (int mb = 0; mb < 4; mb++) {
            #pragma unroll
            for (int h = 0; h < 2; h++) {
                const int row = m0 + m_w + mb * 16 + g + h * 8;
                float2 o;
                o.x = acc[mb][nb][h * 2 + 0] + bb.x;
                o.y = acc[mb][nb][h * 2 + 1] + bb.y;
                *(float2*)(base + (size_t)row * HEAD) = o;
            }
        }
    }
}

// ---------------------------------------------------------------------------
// Kernel 2: fused causal flash attention via mma.sync tf32.
// One CTA per batch, 8 warps. Warp w owns 32-row query block
// qb = (w<4 ? w : 11-w)  (SMSP pairs (w, w+4) both sum to 9 key-blocks).
// Per key block j<=qb: S=Q@K^T (mma), online softmax in C-fragment layout,
// P -> warp-private smem (layout bridge), O += P@V (mma).
// ---------------------------------------------------------------------------
#define SK 68
#define SV 72
#define SQP 68
#define ATT_SMEM_FLOATS (SEQ * SK + SEQ * SV + SEQ * SQP)  // 53248 -> 212992 B

__global__ __launch_bounds__(256, 1) void attn_tc(float* __restrict__ out)
{
    extern __shared__ float sm[];
    float* Ks = sm;                      // [256][68] tf32-rounded K
    float* Vs = Ks + SEQ * SK;           // [256][72] tf32-rounded V
    float* Qs = Vs + SEQ * SV;           // [256][68] tf32(scaled Q); later P

    const int b    = blockIdx.x;
    const int tid  = threadIdx.x;
    const int w    = tid >> 5;
    const int lane = tid & 31;
    const int g    = lane >> 2;
    const int tg   = lane & 3;

    const float qscale = 0.125f * 1.44269504088896340736f;  // SCALE * log2(e)

    // ---- stage K, V, Q (rounded; Q pre-scaled) ----
    {
        const float4* Kg = (const float4*)(g_K + (size_t)b * SEQ * HEAD);
        const float4* Vg = (const float4*)(g_V + (size_t)b * SEQ * HEAD);
        const float4* Qg = (const float4*)(g_Q + (size_t)b * SEQ * HEAD);
        for (int i = tid; i < SEQ * 16; i += 256) {
            const int row = i >> 4;
            const int c   = (i & 15) * 4;
            float4 kv = Kg[i];
            kv.x = f2tf32f(kv.x); kv.y = f2tf32f(kv.y);
            kv.z = f2tf32f(kv.z); kv.w = f2tf32f(kv.w);
            *(float4*)(Ks + row * SK + c) = kv;
            float4 vv = Vg[i];
            vv.x = f2tf32f(vv.x); vv.y = f2tf32f(vv.y);
            vv.z = f2tf32f(vv.z); vv.w = f2tf32f(vv.w);
            *(float4*)(Vs + row * SV + c) = vv;
            float4 qv = Qg[i];
            qv.x = f2tf32f(qv.x * qscale); qv.y = f2tf32f(qv.y * qscale);
            qv.z = f2tf32f(qv.z * qscale); qv.w = f2tf32f(qv.w * qscale);
            *(float4*)(Qs + row * SQP + c) = qv;
        }
    }
    __syncthreads();

    const int qb = (w < 4) ? w : 11 - w;
    float* Pw = Qs + qb * 32 * SQP;      // this warp's private 32-row slice

    // ---- load Q fragments (A layout, 8 k-steps x 2 m-tiles) ----
    uint32_t aQ[2][8][4];
    #pragma unroll
    for (int mt = 0; mt < 2; mt++) {
        const int r0 = (qb * 32 + 16 * mt + g) * SQP;
        #pragma unroll
        for (int kt = 0; kt < 8; kt++) {
            const int c0 = 8 * kt + tg;
            aQ[mt][kt][0] = __float_as_uint(Qs[r0 + c0]);
            aQ[mt][kt][1] = __float_as_uint(Qs[r0 + 8 * SQP + c0]);
            aQ[mt][kt][2] = __float_as_uint(Qs[r0 + c0 + 4]);
            aQ[mt][kt][3] = __float_as_uint(Qs[r0 + 8 * SQP + c0 + 4]);
        }
    }
    __syncwarp();

    float m_[2][2], l_[2][2];
    #pragma unroll
    for (int i = 0; i < 2; i++)
        #pragma unroll
        for (int hh = 0; hh < 2; hh++) { m_[i][hh] = -CUDART_INF_F; l_[i][hh] = 0.0f; }

    float O[2][8][4];
    #pragma unroll
    for (int mt = 0; mt < 2; mt++)
        #pragma unroll
        for (int nh = 0; nh < 8; nh++)
            #pragma unroll
            for (int e = 0; e < 4; e++) O[mt][nh][e] = 0.0f;

    for (int j = 0; j <= qb; j++) {
        // ---- S = Q @ K_j^T ----
        float sc[2][4][4];
        #pragma unroll
        for (int mt = 0; mt < 2; mt++)
            #pragma unroll
            for (int nt = 0; nt < 4; nt++)
                #pragma unroll
                for (int e = 0; e < 4; e++) sc[mt][nt][e] = 0.0f;

        #pragma unroll
        for (int kt = 0; kt < 8; kt++) {
            uint32_t bK[4][2];
            #pragma unroll
            for (int nt = 0; nt < 4; nt++) {
                const int r = (j * 32 + 8 * nt + g) * SK + 8 * kt + tg;
                bK[nt][0] = __float_as_uint(Ks[r]);
                bK[nt][1] = __float_as_uint(Ks[r + 4]);
            }
            #pragma unroll
            for (int mt = 0; mt < 2; mt++)
                #pragma unroll
                for (int nt = 0; nt < 4; nt++)
                    mma_tf32(sc[mt][nt], aQ[mt][kt], bK[nt]);
        }

        // ---- causal mask on diagonal block ----
        if (j == qb) {
            #pragma unroll
            for (int mt = 0; mt < 2; mt++)
                #pragma unroll
                for (int nt = 0; nt < 4; nt++)
                    #pragma unroll
                    for (int hh = 0; hh < 2; hh++)
                        #pragma unroll
                        for (int e = 0; e < 2; e++) {
                            const int rloc = 16 * mt + 8 * hh + g;
                            const int cloc = 8 * nt + 2 * tg + e;
                            if (cloc > rloc) sc[mt][nt][2 * hh + e] = -CUDART_INF_F;
                        }
        }

        // ---- online softmax (per row state: mt x hh) ----
        #pragma unroll
        for (int mt = 0; mt < 2; mt++) {
            #pragma unroll
            for (int hh = 0; hh < 2; hh++) {
                float rm = sc[mt][0][2 * hh];
                #pragma unroll
                for (int nt = 0; nt < 4; nt++) {
                    rm = fmaxf(rm, sc[mt][nt][2 * hh]);
                    rm = fmaxf(rm, sc[mt][nt][2 * hh + 1]);
                }
                rm = fmaxf(rm, __shfl_xor_sync(0xffffffffu, rm, 1));
                rm = fmaxf(rm, __shfl_xor_sync(0xffffffffu, rm, 2));
                const float nm = fmaxf(m_[mt][hh], rm);
                const float cc = exp2f(m_[mt][hh] - nm);   // 0 on first block
                m_[mt][hh] = nm;
                l_[mt][hh] *= cc;
                #pragma unroll
                for (int nh = 0; nh < 8; nh++) {
                    O[mt][nh][2 * hh]     *= cc;
                    O[mt][nh][2 * hh + 1] *= cc;
                }
                float rs = 0.0f;
                #pragma unroll
                for (int nt = 0; nt < 4; nt++) {
                    #pragma unroll
                    for (int e = 0; e < 2; e++) {
                        float p = exp2f(sc[mt][nt][2 * hh + e] - nm);
                        p = f2tf32f(p);          // round exactly as mma will see it
                        rs += p;
                        sc[mt][nt][2 * hh + e] = p;
                    }
                }
                rs += __shfl_xor_sync(0xffffffffu, rs, 1);
                rs += __shfl_xor_sync(0xffffffffu, rs, 2);
                l_[mt][hh] += rs;
            }
        }

        // ---- store P to warp-private smem (C layout -> A layout bridge) ----
        #pragma unroll
        for (int mt = 0; mt < 2; mt++)
            #pragma unroll
            for (int hh = 0; hh < 2; hh++)
                #pragma unroll
                for (int nt = 0; nt < 4; nt++) {
                    float2 pp;
                    pp.x = sc[mt][nt][2 * hh];
                    pp.y = sc[mt][nt][2 * hh + 1];
                    *(float2*)(Pw + (16 * mt + 8 * hh + g) * SQP + 8 * nt + 2 * tg) = pp;
                }
        __syncwarp();

        // ---- O += P @ V_j ----
        #pragma unroll
        for (int kt2 = 0; kt2 < 4; kt2++) {
            uint32_t aP[2][4];
            #pragma unroll
            for (int mt = 0; mt < 2; mt++) {
                const int base = (16 * mt + g) * SQP + 8 * kt2 + tg;
                aP[mt][0] = __float_as_uint(Pw[base]);
                aP[mt][1] = __float_as_uint(Pw[base + 8 * SQP]);
                aP[mt][2] = __float_as_uint(Pw[base + 4]);
                aP[mt][3] = __float_as_uint(Pw[base + 8 * SQP + 4]);
            }
            #pragma unroll
            for (int nh = 0; nh < 8; nh++) {
                uint32_t bV[2];
                const int rv = (j * 32 + 8 * kt2 + tg) * SV + 8 * nh + g;
                bV[0] = __float_as_uint(Vs[rv]);
                bV[1] = __float_as_uint(Vs[rv + 4 * SV]);
                #pragma unroll
                for (int mt = 0; mt < 2; mt++)
                    mma_tf32(O[mt][nh], aP[mt], bV);
            }
        }
        __syncwarp();
    }

    // ---- epilogue: normalize + store ----
    #pragma unroll
    for (int mt = 0; mt < 2; mt++) {
        #pragma unroll
        for (int hh = 0; hh < 2; hh++) {
            const float inv = 1.0f / l_[mt][hh];
            const size_t row = (size_t)b * SEQ + qb * 32 + 16 * mt + 8 * hh + g;
            #pragma unroll
            for (int nh = 0; nh < 8; nh++) {
                float2 o;
                o.x = O[mt][nh][2 * hh]     * inv;
                o.y = O[mt][nh][2 * hh + 1] * inv;
                *(float2*)(out + row * HEAD + 8 * nh + 2 * tg) = o;
            }
        }
    }
}

// ---------------------------------------------------------------------------
extern "C" void kernel_launch(void* const* d_in, const int* in_sizes, int n_in,
                              void* d_out, int out_size)
{
    const float* x  = (const float*)d_in[0];
    const float* Wq = (const float*)d_in[1];
    const float* bq = (const float*)d_in[2];
    const float* Wk = (const float*)d_in[3];
    const float* bk = (const float*)d_in[4];
    const float* Wv = (const float*)d_in[5];
    const float* bv = (const float*)d_in[6];
    float* out = (float*)d_out;

    prep_w<<<(EMBD * NQ + 255) / 256, 256>>>(Wq, bq, Wk, bk, Wv, bv);

    const int qkv_smem = QKV_SMEM_FLOATS * (int)sizeof(float);  // 88064
    cudaFuncSetAttribute(qkv_tc,
                         cudaFuncAttributeMaxDynamicSharedMemorySize, qkv_smem);
    qkv_tc<<<MROWS / TMQ, 256, qkv_smem>>>(x);

    const int att_smem = ATT_SMEM_FLOATS * (int)sizeof(float);  // 212992
    cudaFuncSetAttribute(attn_tc,
                         cudaFuncAttributeMaxDynamicSharedMemorySize, att_smem);
    attn_tc<<<BATCH, 256, att_smem>>>(out);
}

// round 6
// speedup vs baseline: 5.7117x; 1.5816x over previous
#include <cuda_runtime.h>
#include <cuda_fp16.h>
#include <math_constants.h>
#include <cstdint>

#define BATCH 512
#define SEQ   256
#define EMBD  384
#define HEAD  64
#define NQ    192            // Q|K|V concatenated output columns
#define MROWS (BATCH * SEQ)  // 131072
#define TMQ   128            // CTA M tile
#define TK    32             // K chunk
#define KCH   (EMBD / TK)    // 12

// Scratch (allocation-free rule: device globals)
__device__ __half g_Qh[MROWS * HEAD];   // pre-scaled Q, half
__device__ __half g_Kh[MROWS * HEAD];   // K, half
__device__ float  g_V [MROWS * HEAD];   // V, fp32
__device__ __half g_Wh[NQ * EMBD];      // n-major concat weights [n][k], half
__device__ float  g_bc[NQ];             // concat bias (fp32)

// ---------------------------------------------------------------------------
// helpers
// ---------------------------------------------------------------------------
__device__ __forceinline__ uint32_t packh2(float lo, float hi) {
    __half2 h = __floats2half2_rn(lo, hi);
    return reinterpret_cast<uint32_t&>(h);
}
#define CP_ASYNC16(dst, src) \
    asm volatile("cp.async.cg.shared.global [%0], [%1], 16;" \
                 :: "r"((uint32_t)(dst)), "l"(src) : "memory")
#define CP_COMMIT() asm volatile("cp.async.commit_group;" ::: "memory")
#define CP_WAIT(n)  asm volatile("cp.async.wait_group %0;" :: "n"(n) : "memory")

__device__ __forceinline__ uint32_t smem_u32(const void* p) {
    uint32_t a;
    asm("{ .reg .u64 t; cvta.to.shared.u64 t, %1; cvt.u32.u64 %0, t; }"
        : "=r"(a) : "l"(p));
    return a;
}

__device__ __forceinline__ void mma_f16(float* d, const uint32_t* a, const uint32_t* b) {
    asm volatile(
        "mma.sync.aligned.m16n8k16.row.col.f32.f16.f16.f32 "
        "{%0,%1,%2,%3}, {%4,%5,%6,%7}, {%8,%9}, {%0,%1,%2,%3};"
        : "+f"(d[0]), "+f"(d[1]), "+f"(d[2]), "+f"(d[3])
        : "r"(a[0]), "r"(a[1]), "r"(a[2]), "r"(a[3]), "r"(b[0]), "r"(b[1]));
}

// ---------------------------------------------------------------------------
// Kernel 0: concat weights to n-major half [n][k], concat bias fp32
// ---------------------------------------------------------------------------
__global__ __launch_bounds__(256) void prep_w(
    const float* __restrict__ Wq, const float* __restrict__ bq,
    const float* __restrict__ Wk, const float* __restrict__ bk,
    const float* __restrict__ Wv, const float* __restrict__ bv)
{
    int idx = blockIdx.x * 256 + threadIdx.x;
    if (idx < NQ * EMBD) {
        int n = idx / EMBD;
        int k = idx - n * EMBD;
        const float* W = (n < 64) ? Wq : (n < 128) ? Wk : Wv;
        g_Wh[idx] = __float2half_rn(W[k * HEAD + (n & 63)]);
    }
    if (idx < NQ) {
        const float* bb = (idx < 64) ? bq : (idx < 128) ? bk : bv;
        g_bc[idx] = bb[idx & 63];
    }
}

// ---------------------------------------------------------------------------
// Kernel 1: QKV projection via mma.sync fp16 (m16n8k16, fp32 accum).
// CTA: [128 x 192] tile, 8 warps (2 M x 4 N), warp tile 64x48.
// A (x) staged fp32 (stride 40, LDS.64 conflict-free), packed to half2 in reg.
// B (W) staged half via cp.async (stride 56 halfs, conflict-free).
// Epilogue: Q (cols<64) scaled+half -> g_Qh, K half -> g_Kh, V fp32 -> g_V.
// ---------------------------------------------------------------------------
#define A_STRIDE 40                         // fp32 units
#define B_STRIDE 56                         // half units
#define XS_FLOATS (TMQ * A_STRIDE)          // 5120 per buffer
#define WS_HALFS  (NQ * B_STRIDE)           // 10752 per buffer
#define QKV_SMEM_BYTES (2 * XS_FLOATS * 4 + 2 * WS_HALFS * 2)  // 83968

__global__ __launch_bounds__(256, 1) void qkv_tc(const float* __restrict__ x)
{
    extern __shared__ char smraw[];
    float*  xs = (float*)smraw;                       // 2 x [128][40] fp32
    __half* ws = (__half*)(smraw + 2 * XS_FLOATS * 4);// 2 x [192][56] half

    const int tid  = threadIdx.x;
    const int w    = tid >> 5;
    const int lane = tid & 31;
    const int g    = lane >> 2;     // 0..7
    const int tg   = lane & 3;      // 0..3
    const int m0   = blockIdx.x * TMQ;
    const int m_w  = (w & 1) * 64;
    const int n_w  = (w >> 1) * 48;

    uint32_t xs_b = smem_u32(xs);
    uint32_t ws_b = smem_u32(ws);

    float acc[4][6][4];
    #pragma unroll
    for (int mb = 0; mb < 4; mb++)
        #pragma unroll
        for (int nb = 0; nb < 6; nb++)
            #pragma unroll
            for (int i = 0; i < 4; i++) acc[mb][nb][i] = 0.0f;

    // A: 128 rows x 8 quads (16B) = 1024 chunks, 4/thread.
    // B: 192 rows x 4 quads (16B of half) = 768 chunks, 3/thread.
#define STAGE(kc, st) do {                                                     \
        const int _k0 = (kc) * TK;                                             \
        _Pragma("unroll")                                                      \
        for (int _j = 0; _j < 4; _j++) {                                       \
            int _idx = tid + _j * 256;                                         \
            int _r = _idx >> 3, _q = _idx & 7;                                 \
            uint32_t _ad = xs_b + 4 * ((st) * XS_FLOATS + _r * A_STRIDE + 4 * _q); \
            CP_ASYNC16(_ad, (const char*)(x + (size_t)(m0 + _r) * EMBD + _k0 + 4 * _q)); \
        }                                                                      \
        _Pragma("unroll")                                                      \
        for (int _j = 0; _j < 3; _j++) {                                       \
            int _idx = tid + _j * 256;                                         \
            int _n = _idx >> 2, _c = _idx & 3;                                 \
            uint32_t _bd = ws_b + 2 * ((st) * WS_HALFS + _n * B_STRIDE + 8 * _c); \
            CP_ASYNC16(_bd, (const char*)(g_Wh + (size_t)_n * EMBD + _k0 + 8 * _c)); \
        }                                                                      \
        CP_COMMIT();                                                           \
    } while (0)

    STAGE(0, 0);

    for (int kc = 0; kc < KCH; kc++) {
        const int st = kc & 1;
        if (kc + 1 < KCH) {
            STAGE(kc + 1, st ^ 1);
            CP_WAIT(1);
        } else {
            CP_WAIT(0);
        }
        __syncthreads();

        const float*  As = xs + st * XS_FLOATS;
        const __half* Bs = ws + st * WS_HALFS;

        #pragma unroll
        for (int s = 0; s < 2; s++) {            // two k16 steps per 32-chunk
            const int ks = 16 * s;
            uint32_t bf[6][2];
            #pragma unroll
            for (int nb = 0; nb < 6; nb++) {
                const int n = n_w + 8 * nb + g;
                bf[nb][0] = *(const uint32_t*)(Bs + n * B_STRIDE + ks + 2 * tg);
                bf[nb][1] = *(const uint32_t*)(Bs + n * B_STRIDE + ks + 2 * tg + 8);
            }
            #pragma unroll
            for (int mb = 0; mb < 4; mb++) {
                const int rb = m_w + 16 * mb;
                uint32_t af[4];
                {
                    float2 p0 = *(const float2*)(As + (rb + g)     * A_STRIDE + ks + 2 * tg);
                    float2 p1 = *(const float2*)(As + (rb + g + 8) * A_STRIDE + ks + 2 * tg);
                    float2 p2 = *(const float2*)(As + (rb + g)     * A_STRIDE + ks + 2 * tg + 8);
                    float2 p3 = *(const float2*)(As + (rb + g + 8) * A_STRIDE + ks + 2 * tg + 8);
                    af[0] = packh2(p0.x, p0.y);
                    af[1] = packh2(p1.x, p1.y);
                    af[2] = packh2(p2.x, p2.y);
                    af[3] = packh2(p3.x, p3.y);
                }
                #pragma unroll
                for (int nb = 0; nb < 6; nb++)
                    mma_f16(acc[mb][nb], af, bf[nb]);
            }
        }
        __syncthreads();
    }
#undef STAGE

    // Epilogue: bias; Q scaled+half, K half, V fp32
    const float qscale = 0.125f * 1.44269504088896340736f;  // SCALE * log2(e)
    #pragma unroll
    for (int nb = 0; nb < 6; nb++) {
        const int col = n_w + nb * 8 + tg * 2;
        const float2 bb = *(const float2*)(g_bc + col);
        #pragma unroll
        for (int mb = 0; mb < 4; mb++) {
            #pragma unroll
            for (int h = 0; h < 2; h++) {
                const size_t row = m0 + m_w + mb * 16 + g + h * 8;
                float ox = acc[mb][nb][h * 2 + 0] + bb.x;
                float oy = acc[mb][nb][h * 2 + 1] + bb.y;
                if (col < 64) {
                    __half2 v = __floats2half2_rn(ox * qscale, oy * qscale);
                    *(__half2*)(g_Qh + row * HEAD + col) = v;
                } else if (col < 128) {
                    __half2 v = __floats2half2_rn(ox, oy);
                    *(__half2*)(g_Kh + row * HEAD + (col - 64)) = v;
                } else {
                    float2 o = {ox, oy};
                    *(float2*)(g_V + row * HEAD + (col - 128)) = o;
                }
            }
        }
    }
}

// ---------------------------------------------------------------------------
// Kernel 2: fused causal flash attention via mma.sync fp16.
// One CTA per batch, 8 warps; warp w owns query block qb=(w<4?w:11-w).
// K,Q in half smem (stride 72 halfs), V fp32 (stride 68), P bridged half.
// ---------------------------------------------------------------------------
#define SKH 72     // half units
#define SVF 68     // fp32 units
#define ATT_SMEM_BYTES (SEQ * SKH * 2 * 2 + SEQ * SVF * 4)   // 143360

__global__ __launch_bounds__(256, 1) void attn_tc(float* __restrict__ out)
{
    extern __shared__ char smraw[];
    __half* Ks = (__half*)smraw;               // [256][72]
    __half* Qs = Ks + SEQ * SKH;               // [256][72]; later P bridge
    float*  Vs = (float*)(Qs + SEQ * SKH);     // [256][68]

    const int b    = blockIdx.x;
    const int tid  = threadIdx.x;
    const int w    = tid >> 5;
    const int lane = tid & 31;
    const int g    = lane >> 2;
    const int tg   = lane & 3;

    // ---- stage K, Q (half copies), V (fp32 copy) ----
    {
        const uint4* Kg = (const uint4*)(g_Kh + (size_t)b * SEQ * HEAD);
        const uint4* Qg = (const uint4*)(g_Qh + (size_t)b * SEQ * HEAD);
        #pragma unroll
        for (int j = 0; j < 8; j++) {
            int idx = tid + j * 256;           // 2048 chunks of 8 halfs
            int row = idx >> 3, c = idx & 7;
            *(uint4*)(Ks + row * SKH + 8 * c) = Kg[idx];
            *(uint4*)(Qs + row * SKH + 8 * c) = Qg[idx];
        }
        const float4* Vg = (const float4*)(g_V + (size_t)b * SEQ * HEAD);
        #pragma unroll
        for (int j = 0; j < 16; j++) {
            int idx = tid + j * 256;           // 4096 chunks of 4 floats
            int row = idx >> 4, c = idx & 15;
            *(float4*)(Vs + row * SVF + 4 * c) = Vg[idx];
        }
    }
    __syncthreads();

    const int qb = (w < 4) ? w : 11 - w;
    __half* Pw = Qs + qb * 32 * SKH;           // warp-private 32-row slice

    // ---- preload Q fragments (A layout, 4 k16-steps x 2 m-tiles) ----
    uint32_t aQ[2][4][4];
    #pragma unroll
    for (int mt = 0; mt < 2; mt++) {
        const int r0 = (qb * 32 + 16 * mt + g) * SKH;
        #pragma unroll
        for (int kt = 0; kt < 4; kt++) {
            const int c0 = 16 * kt + 2 * tg;
            aQ[mt][kt][0] = *(const uint32_t*)(Qs + r0 + c0);
            aQ[mt][kt][1] = *(const uint32_t*)(Qs + r0 + 8 * SKH + c0);
            aQ[mt][kt][2] = *(const uint32_t*)(Qs + r0 + c0 + 8);
            aQ[mt][kt][3] = *(const uint32_t*)(Qs + r0 + 8 * SKH + c0 + 8);
        }
    }
    __syncwarp();

    float m_[2][2], l_[2][2];
    #pragma unroll
    for (int i = 0; i < 2; i++)
        #pragma unroll
        for (int hh = 0; hh < 2; hh++) { m_[i][hh] = -CUDART_INF_F; l_[i][hh] = 0.0f; }

    float O[2][8][4];
    #pragma unroll
    for (int mt = 0; mt < 2; mt++)
        #pragma unroll
        for (int nh = 0; nh < 8; nh++)
            #pragma unroll
            for (int e = 0; e < 4; e++) O[mt][nh][e] = 0.0f;

    for (int j = 0; j <= qb; j++) {
        // ---- S = Q @ K_j^T ----
        float sc[2][4][4];
        #pragma unroll
        for (int mt = 0; mt < 2; mt++)
            #pragma unroll
            for (int nt = 0; nt < 4; nt++)
                #pragma unroll
                for (int e = 0; e < 4; e++) sc[mt][nt][e] = 0.0f;

        #pragma unroll
        for (int kt = 0; kt < 4; kt++) {
            uint32_t bK[4][2];
            #pragma unroll
            for (int nt = 0; nt < 4; nt++) {
                const int r = (j * 32 + 8 * nt + g) * SKH + 16 * kt + 2 * tg;
                bK[nt][0] = *(const uint32_t*)(Ks + r);
                bK[nt][1] = *(const uint32_t*)(Ks + r + 8);
            }
            #pragma unroll
            for (int mt = 0; mt < 2; mt++)
                #pragma unroll
                for (int nt = 0; nt < 4; nt++)
                    mma_f16(sc[mt][nt], aQ[mt][kt], bK[nt]);
        }

        // ---- causal mask on diagonal block ----
        if (j == qb) {
            #pragma unroll
            for (int mt = 0; mt < 2; mt++)
                #pragma unroll
                for (int nt = 0; nt < 4; nt++)
                    #pragma unroll
                    for (int hh = 0; hh < 2; hh++)
                        #pragma unroll
                        for (int e = 0; e < 2; e++) {
                            const int rloc = 16 * mt + 8 * hh + g;
                            const int cloc = 8 * nt + 2 * tg + e;
                            if (cloc > rloc) sc[mt][nt][2 * hh + e] = -CUDART_INF_F;
                        }
        }

        // ---- online softmax (fp32 state) ----
        #pragma unroll
        for (int mt = 0; mt < 2; mt++) {
            #pragma unroll
            for (int hh = 0; hh < 2; hh++) {
                float rm = sc[mt][0][2 * hh];
                #pragma unroll
                for (int nt = 0; nt < 4; nt++) {
                    rm = fmaxf(rm, sc[mt][nt][2 * hh]);
                    rm = fmaxf(rm, sc[mt][nt][2 * hh + 1]);
                }
                rm = fmaxf(rm, __shfl_xor_sync(0xffffffffu, rm, 1));
                rm = fmaxf(rm, __shfl_xor_sync(0xffffffffu, rm, 2));
                const float nm = fmaxf(m_[mt][hh], rm);
                const float cc = exp2f(m_[mt][hh] - nm);   // 0 on first block
                m_[mt][hh] = nm;
                l_[mt][hh] *= cc;
                #pragma unroll
                for (int nh = 0; nh < 8; nh++) {
                    O[mt][nh][2 * hh]     *= cc;
                    O[mt][nh][2 * hh + 1] *= cc;
                }
                float rs = 0.0f;
                #pragma unroll
                for (int nt = 0; nt < 4; nt++) {
                    #pragma unroll
                    for (int e = 0; e < 2; e++) {
                        float p = exp2f(sc[mt][nt][2 * hh + e] - nm);
                        rs += p;
                        sc[mt][nt][2 * hh + e] = p;
                    }
                }
                rs += __shfl_xor_sync(0xffffffffu, rs, 1);
                rs += __shfl_xor_sync(0xffffffffu, rs, 2);
                l_[mt][hh] += rs;
            }
        }

        // ---- store P (half2) to warp-private smem ----
        #pragma unroll
        for (int mt = 0; mt < 2; mt++)
            #pragma unroll
            for (int hh = 0; hh < 2; hh++)
                #pragma unroll
                for (int nt = 0; nt < 4; nt++) {
                    uint32_t pp = packh2(sc[mt][nt][2 * hh], sc[mt][nt][2 * hh + 1]);
                    *(uint32_t*)(Pw + (16 * mt + 8 * hh + g) * SKH + 8 * nt + 2 * tg) = pp;
                }
        __syncwarp();

        // ---- O += P @ V_j ----
        #pragma unroll
        for (int kt2 = 0; kt2 < 2; kt2++) {
            uint32_t aP[2][4];
            #pragma unroll
            for (int mt = 0; mt < 2; mt++) {
                const int base = (16 * mt + g) * SKH + 16 * kt2 + 2 * tg;
                aP[mt][0] = *(const uint32_t*)(Pw + base);
                aP[mt][1] = *(const uint32_t*)(Pw + base + 8 * SKH);
                aP[mt][2] = *(const uint32_t*)(Pw + base + 8);
                aP[mt][3] = *(const uint32_t*)(Pw + base + 8 * SKH + 8);
            }
            const int s0 = j * 32 + 16 * kt2 + 2 * tg;
            #pragma unroll
            for (int nh = 0; nh < 8; nh++) {
                uint32_t bV[2];
                const int cv = 8 * nh + g;
                bV[0] = packh2(Vs[(s0)     * SVF + cv], Vs[(s0 + 1) * SVF + cv]);
                bV[1] = packh2(Vs[(s0 + 8) * SVF + cv], Vs[(s0 + 9) * SVF + cv]);
                #pragma unroll
                for (int mt = 0; mt < 2; mt++)
                    mma_f16(O[mt][nh], aP[mt], bV);
            }
        }
        __syncwarp();
    }

    // ---- epilogue: normalize + store ----
    #pragma unroll
    for (int mt = 0; mt < 2; mt++) {
        #pragma unroll
        for (int hh = 0; hh < 2; hh++) {
            const float inv = 1.0f / l_[mt][hh];
            const size_t row = (size_t)b * SEQ + qb * 32 + 16 * mt + 8 * hh + g;
            #pragma unroll
            for (int nh = 0; nh < 8; nh++) {
                float2 o;
                o.x = O[mt][nh][2 * hh]     * inv;
                o.y = O[mt][nh][2 * hh + 1] * inv;
                *(float2*)(out + row * HEAD + 8 * nh + 2 * tg) = o;
            }
        }
    }
}

// ---------------------------------------------------------------------------
extern "C" void kernel_launch(void* const* d_in, const int* in_sizes, int n_in,
                              void* d_out, int out_size)
{
    const float* x  = (const float*)d_in[0];
    const float* Wq = (const float*)d_in[1];
    const float* bq = (const float*)d_in[2];
    const float* Wk = (const float*)d_in[3];
    const float* bk = (const float*)d_in[4];
    const float* Wv = (const float*)d_in[5];
    const float* bv = (const float*)d_in[6];
    float* out = (float*)d_out;

    prep_w<<<(NQ * EMBD + 255) / 256, 256>>>(Wq, bq, Wk, bk, Wv, bv);

    cudaFuncSetAttribute(qkv_tc,
                         cudaFuncAttributeMaxDynamicSharedMemorySize, QKV_SMEM_BYTES);
    qkv_tc<<<MROWS / TMQ, 256, QKV_SMEM_BYTES>>>(x);

    cudaFuncSetAttribute(attn_tc,
                         cudaFuncAttributeMaxDynamicSharedMemorySize, ATT_SMEM_BYTES);
    attn_tc<<<BATCH, 256, ATT_SMEM_BYTES>>>(out);
}

// round 8
// speedup vs baseline: 5.7784x; 1.0117x over previous
#include <cuda_runtime.h>
#include <cuda_fp16.h>
#include <math_constants.h>
#include <cstdint>

#define BATCH 512
#define SEQ   256
#define EMBD  384
#define HEAD  64
#define NQ    192            // Q|K|V concatenated output columns
#define MROWS (BATCH * SEQ)  // 131072
#define TMQ   128            // CTA M tile
#define TK    32             // K chunk
#define KCH   (EMBD / TK)    // 12

// Scratch (allocation-free rule: device globals)
__device__ __half g_Qh[MROWS * HEAD];   // pre-scaled Q, half
__device__ __half g_Kh[MROWS * HEAD];   // K, half
__device__ __half g_Vh[MROWS * HEAD];   // V, half
__device__ __half g_Wh[NQ * EMBD];      // n-major concat weights [n][k], half
__device__ float  g_bc[NQ];             // concat bias (fp32)

// ---------------------------------------------------------------------------
// helpers
// ---------------------------------------------------------------------------
__device__ __forceinline__ uint32_t packh2(float lo, float hi) {
    __half2 h = __floats2half2_rn(lo, hi);
    return reinterpret_cast<uint32_t&>(h);
}
#define CP_ASYNC16(dst, src) \
    asm volatile("cp.async.cg.shared.global [%0], [%1], 16;" \
                 :: "r"((uint32_t)(dst)), "l"(src) : "memory")
#define CP_COMMIT() asm volatile("cp.async.commit_group;" ::: "memory")
#define CP_WAIT(n)  asm volatile("cp.async.wait_group %0;" :: "n"(n) : "memory")

__device__ __forceinline__ uint32_t smem_u32(const void* p) {
    uint32_t a;
    asm("{ .reg .u64 t; cvta.to.shared.u64 t, %1; cvt.u32.u64 %0, t; }"
        : "=r"(a) : "l"(p));
    return a;
}
__device__ __forceinline__ void ldm_x4(uint32_t* r, uint32_t addr) {
    asm volatile("ldmatrix.sync.aligned.m8n8.x4.shared.b16 {%0,%1,%2,%3}, [%4];"
        : "=r"(r[0]), "=r"(r[1]), "=r"(r[2]), "=r"(r[3]) : "r"(addr));
}
__device__ __forceinline__ void mma_f16(float* d, const uint32_t* a, const uint32_t* b) {
    asm volatile(
        "mma.sync.aligned.m16n8k16.row.col.f32.f16.f16.f32 "
        "{%0,%1,%2,%3}, {%4,%5,%6,%7}, {%8,%9}, {%0,%1,%2,%3};"
        : "+f"(d[0]), "+f"(d[1]), "+f"(d[2]), "+f"(d[3])
        : "r"(a[0]), "r"(a[1]), "r"(a[2]), "r"(a[3]), "r"(b[0]), "r"(b[1]));
}

// ---------------------------------------------------------------------------
// Kernel 0: concat weights to n-major half [n][k], concat bias fp32
// ---------------------------------------------------------------------------
__global__ __launch_bounds__(256) void prep_w(
    const float* __restrict__ Wq, const float* __restrict__ bq,
    const float* __restrict__ Wk, const float* __restrict__ bk,
    const float* __restrict__ Wv, const float* __restrict__ bv)
{
    int idx = blockIdx.x * 256 + threadIdx.x;
    if (idx < NQ * EMBD) {
        int n = idx / EMBD;
        int k = idx - n * EMBD;
        const float* W = (n < 64) ? Wq : (n < 128) ? Wk : Wv;
        g_Wh[idx] = __float2half_rn(W[k * HEAD + (n & 63)]);
    }
    if (idx < NQ) {
        const float* bb = (idx < 64) ? bq : (idx < 128) ? bk : bv;
        g_bc[idx] = bb[idx & 63];
    }
}

// ---------------------------------------------------------------------------
// Kernel 1: QKV projection via mma.sync fp16 (m16n8k16, fp32 accum).
// CTA: [128 x 192] tile, 8 warps (2 M x 4 N), warp tile 64x48.
// ---------------------------------------------------------------------------
#define A_STRIDE 40                         // fp32 units
#define B_STRIDE 56                         // half units
#define XS_FLOATS (TMQ * A_STRIDE)          // 5120 per buffer
#define WS_HALFS  (NQ * B_STRIDE)           // 10752 per buffer
#define QKV_SMEM_BYTES (2 * XS_FLOATS * 4 + 2 * WS_HALFS * 2)  // 83968

__global__ __launch_bounds__(256, 1) void qkv_tc(const float* __restrict__ x)
{
    extern __shared__ char smraw[];
    float*  xs = (float*)smraw;                       // 2 x [128][40] fp32
    __half* ws = (__half*)(smraw + 2 * XS_FLOATS * 4);// 2 x [192][56] half

    const int tid  = threadIdx.x;
    const int w    = tid >> 5;
    const int lane = tid & 31;
    const int g    = lane >> 2;     // 0..7
    const int tg   = lane & 3;      // 0..3
    const int m0   = blockIdx.x * TMQ;
    const int m_w  = (w & 1) * 64;
    const int n_w  = (w >> 1) * 48;

    uint32_t xs_b = smem_u32(xs);
    uint32_t ws_b = smem_u32(ws);

    float acc[4][6][4];
    #pragma unroll
    for (int mb = 0; mb < 4; mb++)
        #pragma unroll
        for (int nb = 0; nb < 6; nb++)
            #pragma unroll
            for (int i = 0; i < 4; i++) acc[mb][nb][i] = 0.0f;

#define STAGE(kc, st) do {                                                     \
        const int _k0 = (kc) * TK;                                             \
        _Pragma("unroll")                                                      \
        for (int _j = 0; _j < 4; _j++) {                                       \
            int _idx = tid + _j * 256;                                         \
            int _r = _idx >> 3, _q = _idx & 7;                                 \
            uint32_t _ad = xs_b + 4 * ((st) * XS_FLOATS + _r * A_STRIDE + 4 * _q); \
            CP_ASYNC16(_ad, (const char*)(x + (size_t)(m0 + _r) * EMBD + _k0 + 4 * _q)); \
        }                                                                      \
        _Pragma("unroll")                                                      \
        for (int _j = 0; _j < 3; _j++) {                                       \
            int _idx = tid + _j * 256;                                         \
            int _n = _idx >> 2, _c = _idx & 3;                                 \
            uint32_t _bd = ws_b + 2 * ((st) * WS_HALFS + _n * B_STRIDE + 8 * _c); \
            CP_ASYNC16(_bd, (const char*)(g_Wh + (size_t)_n * EMBD + _k0 + 8 * _c)); \
        }                                                                      \
        CP_COMMIT();                                                           \
    } while (0)

    STAGE(0, 0);

    for (int kc = 0; kc < KCH; kc++) {
        const int st = kc & 1;
        if (kc + 1 < KCH) {
            STAGE(kc + 1, st ^ 1);
            CP_WAIT(1);
        } else {
            CP_WAIT(0);
        }
        __syncthreads();

        const float*  As = xs + st * XS_FLOATS;
        const __half* Bs = ws + st * WS_HALFS;

        #pragma unroll
        for (int s = 0; s < 2; s++) {
            const int ks = 16 * s;
            uint32_t bf[6][2];
            #pragma unroll
            for (int nb = 0; nb < 6; nb++) {
                const int n = n_w + 8 * nb + g;
                bf[nb][0] = *(const uint32_t*)(Bs + n * B_STRIDE + ks + 2 * tg);
                bf[nb][1] = *(const uint32_t*)(Bs + n * B_STRIDE + ks + 2 * tg + 8);
            }
            #pragma unroll
            for (int mb = 0; mb < 4; mb++) {
                const int rb = m_w + 16 * mb;
                uint32_t af[4];
                {
                    float2 p0 = *(const float2*)(As + (rb + g)     * A_STRIDE + ks + 2 * tg);
                    float2 p1 = *(const float2*)(As + (rb + g + 8) * A_STRIDE + ks + 2 * tg);
                    float2 p2 = *(const float2*)(As + (rb + g)     * A_STRIDE + ks + 2 * tg + 8);
                    float2 p3 = *(const float2*)(As + (rb + g + 8) * A_STRIDE + ks + 2 * tg + 8);
                    af[0] = packh2(p0.x, p0.y);
                    af[1] = packh2(p1.x, p1.y);
                    af[2] = packh2(p2.x, p2.y);
                    af[3] = packh2(p3.x, p3.y);
                }
                #pragma unroll
                for (int nb = 0; nb < 6; nb++)
                    mma_f16(acc[mb][nb], af, bf[nb]);
            }
        }
        __syncthreads();
    }
#undef STAGE

    // Epilogue: bias; Q scaled+half, K half, V half
    const float qscale = 0.125f * 1.44269504088896340736f;  // SCALE * log2(e)
    #pragma unroll
    for (int nb = 0; nb < 6; nb++) {
        const int col = n_w + nb * 8 + tg * 2;
        const float2 bb = *(const float2*)(g_bc + col);
        #pragma unroll
        for (int mb = 0; mb < 4; mb++) {
            #pragma unroll
            for (int h = 0; h < 2; h++) {
                const size_t row = m0 + m_w + mb * 16 + g + h * 8;
                float ox = acc[mb][nb][h * 2 + 0] + bb.x;
                float oy = acc[mb][nb][h * 2 + 1] + bb.y;
                if (col < 64) {
                    __half2 v = __floats2half2_rn(ox * qscale, oy * qscale);
                    *(__half2*)(g_Qh + row * HEAD + col) = v;
                } else if (col < 128) {
                    __half2 v = __floats2half2_rn(ox, oy);
                    *(__half2*)(g_Kh + row * HEAD + (col - 64)) = v;
                } else {
                    __half2 v = __floats2half2_rn(ox, oy);
                    *(__half2*)(g_Vh + row * HEAD + (col - 128)) = v;
                }
            }
        }
    }
}

// ---------------------------------------------------------------------------
// Kernel 2: fused causal flash attention, mma.sync fp16, 16 warps / CTA.
// Warp w owns 16-row query block qw = (w<8 ? w : 23-w); each SMSP's 4 warps
// sum to exactly 34 key-blocks. All fragment loads via ldmatrix.
// smem: Ks [256][72]h, P/Q slices 16x[16][72]h, Vt [64][266]h (transposed V).
// ---------------------------------------------------------------------------
#define SKH   72                 // half units (K rows, P rows)
#define VTS   266                // half units (Vt rows)
#define PQ_OFF   (SEQ * SKH)                   // 18432 halfs
#define VT_OFF   (PQ_OFF + 16 * 16 * SKH)      // 36864 halfs
#define ATT_SMEM_BYTES ((VT_OFF + HEAD * VTS) * 2)   // 107776

__global__ __launch_bounds__(512, 1) void attn_tc(float* __restrict__ out)
{
    extern __shared__ __half sh[];
    __half* Ks = sh;                 // [256][72]
    __half* Ps = sh + PQ_OFF;        // 16 x [16][72] (Q staging, then P bridge)
    __half* Vt = sh + VT_OFF;        // [64][266]

    const int b    = blockIdx.x;
    const int tid  = threadIdx.x;
    const int w    = tid >> 5;
    const int lane = tid & 31;
    const int g    = lane >> 2;
    const int tg   = lane & 3;

    const uint32_t ks_b = smem_u32(Ks);
    const uint32_t ps_b = smem_u32(Ps);

    // ---- stage K (vectorized) and Vt (transposed scalar) ----
    {
        const uint4* Kg = (const uint4*)(g_Kh + (size_t)b * SEQ * HEAD);
        #pragma unroll
        for (int j = 0; j < 4; j++) {
            int idx = tid + j * 512;           // 2048 chunks of 8 halfs
            int row = idx >> 3, c = idx & 7;
            *(uint4*)(Ks + row * SKH + 8 * c) = Kg[idx];
        }
        const uint4* Vg = (const uint4*)(g_Vh + (size_t)b * SEQ * HEAD);
        #pragma unroll
        for (int j = 0; j < 4; j++) {
            int idx = tid + j * 512;
            int s = idx >> 3, c = idx & 7;
            uint4 v = Vg[idx];
            const __half* hv = (const __half*)&v;
            #pragma unroll
            for (int i = 0; i < 8; i++)
                Vt[(8 * c + i) * VTS + s] = hv[i];
        }
    }

    const int qw = (w < 8) ? w : 23 - w;
    __half* Pw = Ps + qw * 16 * SKH;           // warp-private [16][72]
    const uint32_t pw_b = ps_b + qw * 16 * SKH * 2;

    // ---- stage this warp's Q block into its P slice (warp-local) ----
    {
        const uint4* Qg = (const uint4*)(g_Qh + ((size_t)b * SEQ + qw * 16) * HEAD);
        #pragma unroll
        for (int j = 0; j < 4; j++) {
            int idx = lane + j * 32;           // 128 chunks (16 rows x 8)
            int row = idx >> 3, c = idx & 7;
            *(uint4*)(Pw + row * SKH + 8 * c) = Qg[idx];
        }
    }
    __syncwarp();

    // ---- aQ fragments: 4 x ldmatrix.x4 (kt 0..3) ----
    uint32_t aQ[4][4];
    {
        const int mat = lane >> 3, r = lane & 7;
        const int row = (mat & 1) * 8 + r;
        #pragma unroll
        for (int kt = 0; kt < 4; kt++) {
            uint32_t addr = pw_b + 2 * (row * SKH + kt * 16 + (mat >> 1) * 8);
            ldm_x4(aQ[kt], addr);
        }
    }
    __syncthreads();   // K/Vt visible to all; Q fragment loads done before P reuse

    float m_[2] = {-CUDART_INF_F, -CUDART_INF_F};
    float l_[2] = {0.0f, 0.0f};
    float O[8][4];
    #pragma unroll
    for (int nh = 0; nh < 8; nh++)
        #pragma unroll
        for (int e = 0; e < 4; e++) O[nh][e] = 0.0f;

    const int lmat = lane >> 3, lr = lane & 7;

    for (int j = 0; j <= qw; j++) {
        // ---- S = Q @ K_j^T  (16x16) ----
        float sc[2][4] = {{0, 0, 0, 0}, {0, 0, 0, 0}};
        #pragma unroll
        for (int kt = 0; kt < 4; kt++) {
            uint32_t bK[4];
            // tiles: (nt0,kh0),(nt0,kh1),(nt1,kh0),(nt1,kh1)
            uint32_t addr = ks_b + 2 * ((16 * j + (lmat >> 1) * 8 + lr) * SKH
                                        + kt * 16 + (lmat & 1) * 8);
            ldm_x4(bK, addr);
            mma_f16(sc[0], aQ[kt], bK);
            mma_f16(sc[1], aQ[kt], bK + 2);
        }

        // ---- causal mask on diagonal block ----
        if (j == qw) {
            #pragma unroll
            for (int nt = 0; nt < 2; nt++)
                #pragma unroll
                for (int hh = 0; hh < 2; hh++)
                    #pragma unroll
                    for (int e = 0; e < 2; e++) {
                        const int rloc = 8 * hh + g;
                        const int cloc = 8 * nt + 2 * tg + e;
                        if (cloc > rloc) sc[nt][2 * hh + e] = -CUDART_INF_F;
                    }
        }

        // ---- online softmax (2 row states) ----
        #pragma unroll
        for (int hh = 0; hh < 2; hh++) {
            float rm = fmaxf(fmaxf(sc[0][2 * hh], sc[0][2 * hh + 1]),
                             fmaxf(sc[1][2 * hh], sc[1][2 * hh + 1]));
            rm = fmaxf(rm, __shfl_xor_sync(0xffffffffu, rm, 1));
            rm = fmaxf(rm, __shfl_xor_sync(0xffffffffu, rm, 2));
            const float nm = fmaxf(m_[hh], rm);
            const float cc = exp2f(m_[hh] - nm);     // 0 on first block
            m_[hh] = nm;
            l_[hh] *= cc;
            #pragma unroll
            for (int nh = 0; nh < 8; nh++) {
                O[nh][2 * hh]     *= cc;
                O[nh][2 * hh + 1] *= cc;
            }
            float rs = 0.0f;
            #pragma unroll
            for (int nt = 0; nt < 2; nt++)
                #pragma unroll
                for (int e = 0; e < 2; e++) {
                    float p = exp2f(sc[nt][2 * hh + e] - nm);
                    rs += p;
                    sc[nt][2 * hh + e] = p;
                }
            rs += __shfl_xor_sync(0xffffffffu, rs, 1);
            rs += __shfl_xor_sync(0xffffffffu, rs, 2);
            l_[hh] += rs;
        }

        // ---- P (half) -> warp-private smem ----
        #pragma unroll
        for (int hh = 0; hh < 2; hh++)
            #pragma unroll
            for (int nt = 0; nt < 2; nt++) {
                uint32_t pp = packh2(sc[nt][2 * hh], sc[nt][2 * hh + 1]);
                *(uint32_t*)(Pw + (8 * hh + g) * SKH + 8 * nt + 2 * tg) = pp;
            }
        __syncwarp();

        // ---- aP fragment (one ldmatrix.x4) ----
        uint32_t aP[4];
        {
            uint32_t addr = pw_b + 2 * (((lmat & 1) * 8 + lr) * SKH + (lmat >> 1) * 8);
            ldm_x4(aP, addr);
        }

        // ---- O += P @ V_j ----
        const int s0 = 16 * j + 2 * tg;
        #pragma unroll
        for (int nh = 0; nh < 8; nh++) {
            uint32_t bV[2];
            const int cv = 8 * nh + g;
            bV[0] = *(const uint32_t*)(Vt + cv * VTS + s0);
            bV[1] = *(const uint32_t*)(Vt + cv * VTS + s0 + 8);
            mma_f16(O[nh], aP, bV);
        }
        __syncwarp();
    }

    // ---- epilogue: normalize + store ----
    #pragma unroll
    for (int hh = 0; hh < 2; hh++) {
        const float inv = 1.0f / l_[hh];
        const size_t row = (size_t)b * SEQ + qw * 16 + 8 * hh + g;
        #pragma unroll
        for (int nh = 0; nh < 8; nh++) {
            float2 o;
            o.x = O[nh][2 * hh]     * inv;
            o.y = O[nh][2 * hh + 1] * inv;
            *(float2*)(out + row * HEAD + 8 * nh + 2 * tg) = o;
        }
    }
}

// ---------------------------------------------------------------------------
extern "C" void kernel_launch(void* const* d_in, const int* in_sizes, int n_in,
                              void* d_out, int out_size)
{
    const float* x  = (const float*)d_in[0];
    const float* Wq = (const float*)d_in[1];
    const float* bq = (const float*)d_in[2];
    const float* Wk = (const float*)d_in[3];
    const float* bk = (const float*)d_in[4];
    const float* Wv = (const float*)d_in[5];
    const float* bv = (const float*)d_in[6];
    float* out = (float*)d_out;

    prep_w<<<(NQ * EMBD + 255) / 256, 256>>>(Wq, bq, Wk, bk, Wv, bv);

    cudaFuncSetAttribute(qkv_tc,
                         cudaFuncAttributeMaxDynamicSharedMemorySize, QKV_SMEM_BYTES);
    qkv_tc<<<MROWS / TMQ, 256, QKV_SMEM_BYTES>>>(x);

    cudaFuncSetAttribute(attn_tc,
                         cudaFuncAttributeMaxDynamicSharedMemorySize, ATT_SMEM_BYTES);
    attn_tc<<<BATCH, 512, ATT_SMEM_BYTES>>>(out);
}